// round 15
// baseline (speedup 1.0000x reference)
#include <cuda_runtime.h>

#define N_NODES 50000
#define N_EDGES 800000
#define D 96
#define WS 100                  // padded weight stride (floats)
#define SCAN_T 1024
#define SCAN_B ((N_NODES + SCAN_T - 1) / SCAN_T)   // 49
#define HS_THREADS (SCAN_B * SCAN_T)               // 50176

typedef unsigned long long u64;

__device__ __align__(16) float g_agg[N_NODES * D];   // gathered mean features
__device__ __align__(16) float g_h[N_NODES * D];     // layer-1 activations
__device__ int g_deg[N_NODES];     // INVARIANT: all-zero at kernel_launch entry
__device__ int g_off[N_NODES + 1];
__device__ int g_cur[N_NODES];                        // placement cursors (seeded)
__device__ int g_src[N_EDGES];                        // CSR: src ids grouped by dst
__device__ int g_part[SCAN_B];
__device__ int g_flag[SCAN_B];     // INVARIANT: all-zero at entry (place clears)
__device__ int g_cnt;              // grid-barrier arrive counter (self-resetting)
__device__ int g_done;             // grid-barrier depart counter (self-resetting)

__device__ __forceinline__ u64 pack2(float lo, float hi) {
    u64 r; asm("mov.b64 %0, {%1, %2};" : "=l"(r) : "f"(lo), "f"(hi)); return r;
}
__device__ __forceinline__ void unpack2(u64 v, float& lo, float& hi) {
    asm("mov.b64 {%0, %1}, %2;" : "=f"(lo), "=f"(hi) : "l"(v));
}
__device__ __forceinline__ void fma2(u64& d, u64 a, u64 b) {
    asm("fma.rn.f32x2 %0, %1, %2, %0;" : "+l"(d) : "l"(a), "l"(b));
}
__device__ __forceinline__ int clampi(int v) {
    return min(max(v, 0), N_NODES - 1);
}

// Per-block edge-width detect: int64 small non-negative ids => odd 32-bit
// words of the first 128 words are all zero. Result broadcast via shared.
__device__ __forceinline__ int block_detect_is64(const int* __restrict__ w) {
    __shared__ int s_is64;
    if (threadIdx.x < 64) {
        int bad = (w[2 * threadIdx.x + 1] != 0) ? 1 : 0;
        unsigned m = __ballot_sync(0xffffffffu, bad);
        __shared__ unsigned sm[2];
        sm[threadIdx.x >> 5] = m;
        __syncwarp();
        if (threadIdx.x == 0) s_is64 = (sm[0] | sm[1]) ? 0 : 1;
    }
    __syncthreads();
    return s_is64;
}

// ---------------------------------------------------------------------------
// Fused histogram + scan. 49 blocks x 1024 threads (all co-resident).
// Phase A: grid-strided int4/longlong2 histogram of dst degrees.
// Grid barrier: arrive counter + spin; last departer resets (replay-safe).
// Phase B: decoupled-lookback exclusive scan; seeds g_cur; re-zeros g_deg.
// ---------------------------------------------------------------------------
__global__ __launch_bounds__(SCAN_T) void histscan_kernel(const void* __restrict__ eiv) {
    int is64 = block_detect_is64((const int*)eiv);
    int g = blockIdx.x * SCAN_T + threadIdx.x;

    // Phase A: histogram (N_EDGES divisible by 4)
#pragma unroll
    for (int r = 0; r < 4; r++) {
        int grp = g + r * HS_THREADS;
        if (grp * 4 + 3 < N_EDGES) {
            int e = grp * 4;
            int d0, d1, d2, d3;
            if (is64) {
                const longlong2* p = (const longlong2*)((const long long*)eiv + N_EDGES + e);
                longlong2 a = p[0], b = p[1];
                d0 = (int)a.x; d1 = (int)a.y; d2 = (int)b.x; d3 = (int)b.y;
            } else {
                int4 a = *(const int4*)((const int*)eiv + N_EDGES + e);
                d0 = a.x; d1 = a.y; d2 = a.z; d3 = a.w;
            }
            atomicAdd(&g_deg[clampi(d0)], 1);
            atomicAdd(&g_deg[clampi(d1)], 1);
            atomicAdd(&g_deg[clampi(d2)], 1);
            atomicAdd(&g_deg[clampi(d3)], 1);
        }
    }

    // Grid barrier
    __syncthreads();
    if (threadIdx.x == 0) {
        __threadfence();
        atomicAdd(&g_cnt, 1);
        while (((volatile int*)&g_cnt)[0] < SCAN_B) {}
        __threadfence();
    }
    __syncthreads();

    // Phase B: scan (identical to proven lookback scan)
    __shared__ int wsum[32];
    __shared__ int red[2];
    __shared__ int sbase;

    int tid = threadIdx.x;
    int bx  = blockIdx.x;
    int i = bx * SCAN_T + tid;
    int v = (i < N_NODES) ? g_deg[i] : 0;
    if (i < N_NODES) g_deg[i] = 0;           // restore invariant

    int s = v;
#pragma unroll
    for (int o = 1; o < 32; o <<= 1) {
        int u = __shfl_up_sync(0xffffffffu, s, o);
        if ((tid & 31) >= o) s += u;
    }
    if ((tid & 31) == 31) wsum[tid >> 5] = s;
    __syncthreads();
    if (tid < 32) {
        int t = wsum[tid];
#pragma unroll
        for (int o = 1; o < 32; o <<= 1) {
            int u = __shfl_up_sync(0xffffffffu, t, o);
            if (tid >= o) t += u;
        }
        wsum[tid] = t;
    }
    __syncthreads();

    if (tid == 0) {
        g_part[bx] = wsum[31];
        __threadfence();
        ((volatile int*)g_flag)[bx] = 1;
    }

    if (tid < 64) {
        int val = 0;
        if (tid < bx) {
            while (((volatile int*)g_flag)[tid] == 0) {}
            __threadfence();
            val = ((volatile int*)g_part)[tid];
        }
#pragma unroll
        for (int o = 16; o > 0; o >>= 1)
            val += __shfl_xor_sync(0xffffffffu, val, o);
        if ((tid & 31) == 0) red[tid >> 5] = val;
    }
    __syncthreads();
    if (tid == 0) sbase = red[0] + red[1];
    __syncthreads();

    int warp = tid >> 5;
    int wbase = warp ? wsum[warp - 1] : 0;
    int excl = sbase + wbase + (s - v);
    if (i < N_NODES) {
        g_off[i] = excl;
        g_cur[i] = excl;
        if (i == N_NODES - 1) g_off[N_NODES] = excl + v;
    }

    // Depart: last block resets barrier counters for the next call
    __syncthreads();
    if (tid == 0) {
        __threadfence();
        int old2 = atomicAdd(&g_done, 1);
        if (old2 == SCAN_B - 1) { g_cnt = 0; g_done = 0; }
    }
}

// ---------------------------------------------------------------------------
// place: 4 edges per thread; atomics on seeded cursors. Clears g_flag.
// ---------------------------------------------------------------------------
__global__ void place_kernel(const void* __restrict__ eiv) {
    int is64 = block_detect_is64((const int*)eiv);
    int gid = blockIdx.x * blockDim.x + threadIdx.x;
    if (gid < SCAN_B) g_flag[gid] = 0;       // restore invariant
    int e = 4 * gid;
    if (e + 3 < N_EDGES) {
        int s0, s1, s2, s3, d0, d1, d2, d3;
        if (is64) {
            const longlong2* sp = (const longlong2*)((const long long*)eiv + e);
            const longlong2* dp = (const longlong2*)((const long long*)eiv + N_EDGES + e);
            longlong2 sa = sp[0], sb = sp[1], da = dp[0], db = dp[1];
            s0 = (int)sa.x; s1 = (int)sa.y; s2 = (int)sb.x; s3 = (int)sb.y;
            d0 = (int)da.x; d1 = (int)da.y; d2 = (int)db.x; d3 = (int)db.y;
        } else {
            int4 sa = *(const int4*)((const int*)eiv + e);
            int4 da = *(const int4*)((const int*)eiv + N_EDGES + e);
            s0 = sa.x; s1 = sa.y; s2 = sa.z; s3 = sa.w;
            d0 = da.x; d1 = da.y; d2 = da.z; d3 = da.w;
        }
        s0 = clampi(s0); s1 = clampi(s1); s2 = clampi(s2); s3 = clampi(s3);
        int p0 = atomicAdd(&g_cur[clampi(d0)], 1);
        int p1 = atomicAdd(&g_cur[clampi(d1)], 1);
        int p2 = atomicAdd(&g_cur[clampi(d2)], 1);
        int p3 = atomicAdd(&g_cur[clampi(d3)], 1);
        if (p0 >= 0 && p0 < N_EDGES) g_src[p0] = s0;
        if (p1 >= 0 && p1 < N_EDGES) g_src[p1] = s1;
        if (p2 >= 0 && p2 < N_EDGES) g_src[p2] = s2;
        if (p3 >= 0 && p3 < N_EDGES) g_src[p3] = s3;
    } else {
        for (int k = e; k < N_EDGES; k++) {
            int src, dst;
            if (is64) {
                src = (int)((const long long*)eiv)[k];
                dst = (int)((const long long*)eiv)[N_EDGES + k];
            } else {
                src = ((const int*)eiv)[k];
                dst = ((const int*)eiv)[N_EDGES + k];
            }
            int pos = atomicAdd(&g_cur[clampi(dst)], 1);
            if (pos >= 0 && pos < N_EDGES) g_src[pos] = clampi(src);
        }
    }
}

// ---------------------------------------------------------------------------
// Gather mean: one warp per node; 24 active lanes, one float4 per lane per
// edge. 8-edge unroll to hide L2 latency.
// ---------------------------------------------------------------------------
__global__ __launch_bounds__(256) void gather_kernel(const float* __restrict__ x,
                                                     int from_h) {
    int warp = (blockIdx.x * blockDim.x + threadIdx.x) >> 5;
    int lane = threadIdx.x & 31;
    if (warp >= N_NODES) return;
    const float* feat = from_h ? (const float*)g_h : x;
    int beg = g_off[warp];
    int end = g_off[warp + 1];
    bool act = lane < 24;
    float4 a = make_float4(0.f, 0.f, 0.f, 0.f);
    float4 b = make_float4(0.f, 0.f, 0.f, 0.f);
    int i = beg;
    for (; i + 7 < end; i += 8) {
        int s0 = g_src[i],     s1 = g_src[i + 1], s2 = g_src[i + 2], s3 = g_src[i + 3];
        int s4 = g_src[i + 4], s5 = g_src[i + 5], s6 = g_src[i + 6], s7 = g_src[i + 7];
        if (act) {
            float4 v0 = ((const float4*)(feat + (size_t)s0 * D))[lane];
            float4 v1 = ((const float4*)(feat + (size_t)s1 * D))[lane];
            float4 v2 = ((const float4*)(feat + (size_t)s2 * D))[lane];
            float4 v3 = ((const float4*)(feat + (size_t)s3 * D))[lane];
            float4 v4 = ((const float4*)(feat + (size_t)s4 * D))[lane];
            float4 v5 = ((const float4*)(feat + (size_t)s5 * D))[lane];
            float4 v6 = ((const float4*)(feat + (size_t)s6 * D))[lane];
            float4 v7 = ((const float4*)(feat + (size_t)s7 * D))[lane];
            a.x += (v0.x + v1.x) + (v2.x + v3.x);
            a.y += (v0.y + v1.y) + (v2.y + v3.y);
            a.z += (v0.z + v1.z) + (v2.z + v3.z);
            a.w += (v0.w + v1.w) + (v2.w + v3.w);
            b.x += (v4.x + v5.x) + (v6.x + v7.x);
            b.y += (v4.y + v5.y) + (v6.y + v7.y);
            b.z += (v4.z + v5.z) + (v6.z + v7.z);
            b.w += (v4.w + v5.w) + (v6.w + v7.w);
        }
    }
    for (; i + 1 < end; i += 2) {
        int s0 = g_src[i], s1 = g_src[i + 1];
        if (act) {
            float4 v0 = ((const float4*)(feat + (size_t)s0 * D))[lane];
            float4 v1 = ((const float4*)(feat + (size_t)s1 * D))[lane];
            a.x += v0.x + v1.x; a.y += v0.y + v1.y;
            a.z += v0.z + v1.z; a.w += v0.w + v1.w;
        }
    }
    if (i < end) {
        int s0 = g_src[i];
        if (act) {
            float4 v0 = ((const float4*)(feat + (size_t)s0 * D))[lane];
            a.x += v0.x; a.y += v0.y; a.z += v0.z; a.w += v0.w;
        }
    }
    if (act) {
        float inv = 1.0f / (float)max(end - beg, 1);
        float4 r;
        r.x = (a.x + b.x) * inv;
        r.y = (a.y + b.y) * inv;
        r.z = (a.z + b.z) * inv;
        r.w = (a.w + b.w) * inv;
        ((float4*)(g_agg + (size_t)warp * D))[lane] = r;
    }
}

// ---------------------------------------------------------------------------
// Fused SAGE linear layer: thread = (node-pair, output-quarter).
// Each thread: 2 nodes x 24 outputs = 24 u64 accs (same regs as before) but
// each weight LDS.128 now feeds 4 FFMA2 (2 nodes) -> per-thread LDS halves.
// 128-thread blocks = 64 nodes/block.
// ---------------------------------------------------------------------------
__global__ __launch_bounds__(128) void gemm_kernel(
    const float* __restrict__ x, int in_h,
    const float* __restrict__ Wl,
    const float* __restrict__ Wr,
    const float* __restrict__ bias,
    float* __restrict__ out, int out_h,
    int apply_elu)
{
    __shared__ __align__(16) float ws[D * WS];   // ws[k*WS + o] = W[o][k]
    __shared__ float bsm[D];

    const float* feat = in_h ? (const float*)g_h : x;
    float* dst = out_h ? (float*)g_h : out;

    for (int i = threadIdx.x; i < D * D; i += 128) {
        int o = i / D, k = i % D;
        ws[k * WS + o] = Wl[i];
    }
    if (threadIdx.x < D) bsm[threadIdx.x] = bias[threadIdx.x];
    __syncthreads();

    int pair  = threadIdx.x >> 2;                // 0..31
    int q     = threadIdx.x & 3;                 // output quarter
    int node0 = blockIdx.x * 64 + pair * 2;
    int node1 = node0 + 1;
    int obase = q * 24;
    bool act0 = node0 < N_NODES;
    bool act1 = node1 < N_NODES;

    u64 acc0[12], acc1[12];
#pragma unroll
    for (int j = 0; j < 12; j++) {
        u64 bv = pack2(bsm[obase + 2 * j], bsm[obase + 2 * j + 1]);
        acc0[j] = bv;
        acc1[j] = bv;
    }

    const float4* a40 = (const float4*)(g_agg + (size_t)node0 * D);
    const float4* a41 = (const float4*)(g_agg + (size_t)node1 * D);
    const float4* f40 = (const float4*)(feat + (size_t)node0 * D);
    const float4* f41 = (const float4*)(feat + (size_t)node1 * D);
    const float4 fz = make_float4(0.f, 0.f, 0.f, 0.f);

    if (act0) {
        float4 av0 = a40[0];
        float4 av1 = act1 ? a41[0] : fz;
#pragma unroll 1
        for (int kb = 0; kb < D / 4; kb++) {
            float4 nx0 = (kb < D / 4 - 1) ? a40[kb + 1] : fz;
            float4 nx1 = (kb < D / 4 - 1 && act1) ? a41[kb + 1] : fz;
            const float* wb = ws + 4 * kb * WS + obase;
#pragma unroll
            for (int kx = 0; kx < 4; kx++) {
                const ulonglong2* wq = (const ulonglong2*)(wb + kx * WS);
                float c0 = (kx == 0) ? av0.x : (kx == 1) ? av0.y : (kx == 2) ? av0.z : av0.w;
                float c1 = (kx == 0) ? av1.x : (kx == 1) ? av1.y : (kx == 2) ? av1.z : av1.w;
                u64 a0 = pack2(c0, c0);
                u64 a1 = pack2(c1, c1);
#pragma unroll
                for (int j = 0; j < 6; j++) {
                    ulonglong2 w = wq[j];
                    fma2(acc0[2 * j], a0, w.x); fma2(acc0[2 * j + 1], a0, w.y);
                    fma2(acc1[2 * j], a1, w.x); fma2(acc1[2 * j + 1], a1, w.y);
                }
            }
            av0 = nx0;
            av1 = nx1;
        }
    }

    // Prefetch phase-2 first activations under the restage barrier
    float4 pv0 = act0 ? f40[0] : fz;
    float4 pv1 = act1 ? f41[0] : fz;

    __syncthreads();
    for (int i = threadIdx.x; i < D * D; i += 128) {
        int o = i / D, k = i % D;
        ws[k * WS + o] = Wr[i];
    }
    __syncthreads();

    if (act0) {
        float4 av0 = pv0;
        float4 av1 = pv1;
#pragma unroll 1
        for (int kb = 0; kb < D / 4; kb++) {
            float4 nx0 = (kb < D / 4 - 1) ? f40[kb + 1] : fz;
            float4 nx1 = (kb < D / 4 - 1 && act1) ? f41[kb + 1] : fz;
            const float* wb = ws + 4 * kb * WS + obase;
#pragma unroll
            for (int kx = 0; kx < 4; kx++) {
                const ulonglong2* wq = (const ulonglong2*)(wb + kx * WS);
                float c0 = (kx == 0) ? av0.x : (kx == 1) ? av0.y : (kx == 2) ? av0.z : av0.w;
                float c1 = (kx == 0) ? av1.x : (kx == 1) ? av1.y : (kx == 2) ? av1.z : av1.w;
                u64 a0 = pack2(c0, c0);
                u64 a1 = pack2(c1, c1);
#pragma unroll
                for (int j = 0; j < 6; j++) {
                    ulonglong2 w = wq[j];
                    fma2(acc0[2 * j], a0, w.x); fma2(acc0[2 * j + 1], a0, w.y);
                    fma2(acc1[2 * j], a1, w.x); fma2(acc1[2 * j + 1], a1, w.y);
                }
            }
            av0 = nx0;
            av1 = nx1;
        }

        // Epilogue node0
        float4* o0 = (float4*)(dst + (size_t)node0 * D + obase);
#pragma unroll
        for (int j = 0; j < 6; j++) {
            float v0, v1, v2, v3;
            unpack2(acc0[2 * j],     v0, v1);
            unpack2(acc0[2 * j + 1], v2, v3);
            if (apply_elu) {
                v0 = v0 > 0.0f ? v0 : expm1f(v0);
                v1 = v1 > 0.0f ? v1 : expm1f(v1);
                v2 = v2 > 0.0f ? v2 : expm1f(v2);
                v3 = v3 > 0.0f ? v3 : expm1f(v3);
            }
            o0[j] = make_float4(v0, v1, v2, v3);
        }
        // Epilogue node1
        if (act1) {
            float4* o1 = (float4*)(dst + (size_t)node1 * D + obase);
#pragma unroll
            for (int j = 0; j < 6; j++) {
                float v0, v1, v2, v3;
                unpack2(acc1[2 * j],     v0, v1);
                unpack2(acc1[2 * j + 1], v2, v3);
                if (apply_elu) {
                    v0 = v0 > 0.0f ? v0 : expm1f(v0);
                    v1 = v1 > 0.0f ? v1 : expm1f(v1);
                    v2 = v2 > 0.0f ? v2 : expm1f(v2);
                    v3 = v3 > 0.0f ? v3 : expm1f(v3);
                }
                o1[j] = make_float4(v0, v1, v2, v3);
            }
        }
    }
}

// ---------------------------------------------------------------------------
// Launch sequence (graph-capturable; kernel launches only). 6 launches;
// gemm1 sits at profile slot #4.
// ---------------------------------------------------------------------------
extern "C" void kernel_launch(void* const* d_in, const int* in_sizes, int n_in,
                              void* d_out, int out_size) {
    const float* x   = (const float*)d_in[0];
    const void*  ei  = d_in[1];
    const float* W1l = (const float*)d_in[2];
    const float* b1  = (const float*)d_in[3];
    const float* W1r = (const float*)d_in[4];
    const float* W2l = (const float*)d_in[5];
    const float* b2  = (const float*)d_in[6];
    const float* W2r = (const float*)d_in[7];
    float*       out = (float*)d_out;

    const int pb = (N_EDGES / 4 + 255) / 256;
    const int wb = (N_NODES * 32 + 255) / 256;
    const int gb = (N_NODES + 63) / 64;          // 64 nodes per 128-thr block

    // CSR build
    histscan_kernel<<<SCAN_B, SCAN_T>>>(ei);            // 1
    place_kernel<<<pb, 256>>>(ei);                      // 2

    // Layer 1
    gather_kernel<<<wb, 256>>>(x, 0);                   // 3
    gemm_kernel<<<gb, 128>>>(x, 0, W1l, W1r, b1, nullptr, 1, 1);   // 4 <- profiled

    // Layer 2
    gather_kernel<<<wb, 256>>>(nullptr, 1);             // 5
    gemm_kernel<<<gb, 128>>>(nullptr, 1, W2l, W2r, b2, out, 0, 0); // 6
}

// round 16
// speedup vs baseline: 1.3596x; 1.3596x over previous
#include <cuda_runtime.h>

#define N_NODES 50000
#define N_EDGES 800000
#define D 96
#define WS 100                  // padded weight stride (floats)
#define TILE_N 64               // nodes per gemm block
#define SCAN_T 1024
#define SCAN_B ((N_NODES + SCAN_T - 1) / SCAN_T)   // 49
#define HS_THREADS (SCAN_B * SCAN_T)               // 50176

typedef unsigned long long u64;

__device__ __align__(16) float g_agg[N_NODES * D];   // gathered mean features
__device__ __align__(16) float g_h[N_NODES * D];     // layer-1 activations
__device__ int g_deg[N_NODES];     // INVARIANT: all-zero at kernel_launch entry
__device__ int g_off[N_NODES + 1];
__device__ int g_cur[N_NODES];                        // placement cursors (seeded)
__device__ int g_src[N_EDGES];                        // CSR: src ids grouped by dst
__device__ int g_part[SCAN_B];
__device__ int g_flag[SCAN_B];     // INVARIANT: all-zero at entry (place clears)
__device__ int g_cnt;              // grid-barrier arrive counter (self-resetting)
__device__ int g_done;             // grid-barrier depart counter (self-resetting)

__device__ __forceinline__ u64 pack2(float lo, float hi) {
    u64 r; asm("mov.b64 %0, {%1, %2};" : "=l"(r) : "f"(lo), "f"(hi)); return r;
}
__device__ __forceinline__ void unpack2(u64 v, float& lo, float& hi) {
    asm("mov.b64 {%0, %1}, %2;" : "=f"(lo), "=f"(hi) : "l"(v));
}
__device__ __forceinline__ void fma2(u64& d, u64 a, u64 b) {
    asm("fma.rn.f32x2 %0, %1, %2, %0;" : "+l"(d) : "l"(a), "l"(b));
}
__device__ __forceinline__ int clampi(int v) {
    return min(max(v, 0), N_NODES - 1);
}

// Per-block edge-width detect: int64 small non-negative ids => odd 32-bit
// words of the first 128 words are all zero. Result broadcast via shared.
__device__ __forceinline__ int block_detect_is64(const int* __restrict__ w) {
    __shared__ int s_is64;
    if (threadIdx.x < 64) {
        int bad = (w[2 * threadIdx.x + 1] != 0) ? 1 : 0;
        unsigned m = __ballot_sync(0xffffffffu, bad);
        __shared__ unsigned sm[2];
        sm[threadIdx.x >> 5] = m;
        __syncwarp();
        if (threadIdx.x == 0) s_is64 = (sm[0] | sm[1]) ? 0 : 1;
    }
    __syncthreads();
    return s_is64;
}

// ---------------------------------------------------------------------------
// Fused histogram + scan. 49 blocks x 1024 threads (all co-resident).
// ---------------------------------------------------------------------------
__global__ __launch_bounds__(SCAN_T) void histscan_kernel(const void* __restrict__ eiv) {
    int is64 = block_detect_is64((const int*)eiv);
    int g = blockIdx.x * SCAN_T + threadIdx.x;

#pragma unroll
    for (int r = 0; r < 4; r++) {
        int grp = g + r * HS_THREADS;
        if (grp * 4 + 3 < N_EDGES) {
            int e = grp * 4;
            int d0, d1, d2, d3;
            if (is64) {
                const longlong2* p = (const longlong2*)((const long long*)eiv + N_EDGES + e);
                longlong2 a = p[0], b = p[1];
                d0 = (int)a.x; d1 = (int)a.y; d2 = (int)b.x; d3 = (int)b.y;
            } else {
                int4 a = *(const int4*)((const int*)eiv + N_EDGES + e);
                d0 = a.x; d1 = a.y; d2 = a.z; d3 = a.w;
            }
            atomicAdd(&g_deg[clampi(d0)], 1);
            atomicAdd(&g_deg[clampi(d1)], 1);
            atomicAdd(&g_deg[clampi(d2)], 1);
            atomicAdd(&g_deg[clampi(d3)], 1);
        }
    }

    __syncthreads();
    if (threadIdx.x == 0) {
        __threadfence();
        atomicAdd(&g_cnt, 1);
        while (((volatile int*)&g_cnt)[0] < SCAN_B) {}
        __threadfence();
    }
    __syncthreads();

    __shared__ int wsum[32];
    __shared__ int red[2];
    __shared__ int sbase;

    int tid = threadIdx.x;
    int bx  = blockIdx.x;
    int i = bx * SCAN_T + tid;
    int v = (i < N_NODES) ? g_deg[i] : 0;
    if (i < N_NODES) g_deg[i] = 0;           // restore invariant

    int s = v;
#pragma unroll
    for (int o = 1; o < 32; o <<= 1) {
        int u = __shfl_up_sync(0xffffffffu, s, o);
        if ((tid & 31) >= o) s += u;
    }
    if ((tid & 31) == 31) wsum[tid >> 5] = s;
    __syncthreads();
    if (tid < 32) {
        int t = wsum[tid];
#pragma unroll
        for (int o = 1; o < 32; o <<= 1) {
            int u = __shfl_up_sync(0xffffffffu, t, o);
            if (tid >= o) t += u;
        }
        wsum[tid] = t;
    }
    __syncthreads();

    if (tid == 0) {
        g_part[bx] = wsum[31];
        __threadfence();
        ((volatile int*)g_flag)[bx] = 1;
    }

    if (tid < 64) {
        int val = 0;
        if (tid < bx) {
            while (((volatile int*)g_flag)[tid] == 0) {}
            __threadfence();
            val = ((volatile int*)g_part)[tid];
        }
#pragma unroll
        for (int o = 16; o > 0; o >>= 1)
            val += __shfl_xor_sync(0xffffffffu, val, o);
        if ((tid & 31) == 0) red[tid >> 5] = val;
    }
    __syncthreads();
    if (tid == 0) sbase = red[0] + red[1];
    __syncthreads();

    int warp = tid >> 5;
    int wbase = warp ? wsum[warp - 1] : 0;
    int excl = sbase + wbase + (s - v);
    if (i < N_NODES) {
        g_off[i] = excl;
        g_cur[i] = excl;
        if (i == N_NODES - 1) g_off[N_NODES] = excl + v;
    }

    __syncthreads();
    if (tid == 0) {
        __threadfence();
        int old2 = atomicAdd(&g_done, 1);
        if (old2 == SCAN_B - 1) { g_cnt = 0; g_done = 0; }
    }
}

// ---------------------------------------------------------------------------
// place: 4 edges per thread; atomics on seeded cursors. Clears g_flag.
// ---------------------------------------------------------------------------
__global__ void place_kernel(const void* __restrict__ eiv) {
    int is64 = block_detect_is64((const int*)eiv);
    int gid = blockIdx.x * blockDim.x + threadIdx.x;
    if (gid < SCAN_B) g_flag[gid] = 0;       // restore invariant
    int e = 4 * gid;
    if (e + 3 < N_EDGES) {
        int s0, s1, s2, s3, d0, d1, d2, d3;
        if (is64) {
            const longlong2* sp = (const longlong2*)((const long long*)eiv + e);
            const longlong2* dp = (const longlong2*)((const long long*)eiv + N_EDGES + e);
            longlong2 sa = sp[0], sb = sp[1], da = dp[0], db = dp[1];
            s0 = (int)sa.x; s1 = (int)sa.y; s2 = (int)sb.x; s3 = (int)sb.y;
            d0 = (int)da.x; d1 = (int)da.y; d2 = (int)db.x; d3 = (int)db.y;
        } else {
            int4 sa = *(const int4*)((const int*)eiv + e);
            int4 da = *(const int4*)((const int*)eiv + N_EDGES + e);
            s0 = sa.x; s1 = sa.y; s2 = sa.z; s3 = sa.w;
            d0 = da.x; d1 = da.y; d2 = da.z; d3 = da.w;
        }
        s0 = clampi(s0); s1 = clampi(s1); s2 = clampi(s2); s3 = clampi(s3);
        int p0 = atomicAdd(&g_cur[clampi(d0)], 1);
        int p1 = atomicAdd(&g_cur[clampi(d1)], 1);
        int p2 = atomicAdd(&g_cur[clampi(d2)], 1);
        int p3 = atomicAdd(&g_cur[clampi(d3)], 1);
        if (p0 >= 0 && p0 < N_EDGES) g_src[p0] = s0;
        if (p1 >= 0 && p1 < N_EDGES) g_src[p1] = s1;
        if (p2 >= 0 && p2 < N_EDGES) g_src[p2] = s2;
        if (p3 >= 0 && p3 < N_EDGES) g_src[p3] = s3;
    } else {
        for (int k = e; k < N_EDGES; k++) {
            int src, dst;
            if (is64) {
                src = (int)((const long long*)eiv)[k];
                dst = (int)((const long long*)eiv)[N_EDGES + k];
            } else {
                src = ((const int*)eiv)[k];
                dst = ((const int*)eiv)[N_EDGES + k];
            }
            int pos = atomicAdd(&g_cur[clampi(dst)], 1);
            if (pos >= 0 && pos < N_EDGES) g_src[pos] = clampi(src);
        }
    }
}

// ---------------------------------------------------------------------------
// Gather mean: one warp per node; 24 active lanes, one float4 per lane per
// edge. 8-edge unroll to hide L2 latency.
// ---------------------------------------------------------------------------
__global__ __launch_bounds__(256) void gather_kernel(const float* __restrict__ x,
                                                     int from_h) {
    int warp = (blockIdx.x * blockDim.x + threadIdx.x) >> 5;
    int lane = threadIdx.x & 31;
    if (warp >= N_NODES) return;
    const float* feat = from_h ? (const float*)g_h : x;
    int beg = g_off[warp];
    int end = g_off[warp + 1];
    bool act = lane < 24;
    float4 a = make_float4(0.f, 0.f, 0.f, 0.f);
    float4 b = make_float4(0.f, 0.f, 0.f, 0.f);
    int i = beg;
    for (; i + 7 < end; i += 8) {
        int s0 = g_src[i],     s1 = g_src[i + 1], s2 = g_src[i + 2], s3 = g_src[i + 3];
        int s4 = g_src[i + 4], s5 = g_src[i + 5], s6 = g_src[i + 6], s7 = g_src[i + 7];
        if (act) {
            float4 v0 = ((const float4*)(feat + (size_t)s0 * D))[lane];
            float4 v1 = ((const float4*)(feat + (size_t)s1 * D))[lane];
            float4 v2 = ((const float4*)(feat + (size_t)s2 * D))[lane];
            float4 v3 = ((const float4*)(feat + (size_t)s3 * D))[lane];
            float4 v4 = ((const float4*)(feat + (size_t)s4 * D))[lane];
            float4 v5 = ((const float4*)(feat + (size_t)s5 * D))[lane];
            float4 v6 = ((const float4*)(feat + (size_t)s6 * D))[lane];
            float4 v7 = ((const float4*)(feat + (size_t)s7 * D))[lane];
            a.x += (v0.x + v1.x) + (v2.x + v3.x);
            a.y += (v0.y + v1.y) + (v2.y + v3.y);
            a.z += (v0.z + v1.z) + (v2.z + v3.z);
            a.w += (v0.w + v1.w) + (v2.w + v3.w);
            b.x += (v4.x + v5.x) + (v6.x + v7.x);
            b.y += (v4.y + v5.y) + (v6.y + v7.y);
            b.z += (v4.z + v5.z) + (v6.z + v7.z);
            b.w += (v4.w + v5.w) + (v6.w + v7.w);
        }
    }
    for (; i + 1 < end; i += 2) {
        int s0 = g_src[i], s1 = g_src[i + 1];
        if (act) {
            float4 v0 = ((const float4*)(feat + (size_t)s0 * D))[lane];
            float4 v1 = ((const float4*)(feat + (size_t)s1 * D))[lane];
            a.x += v0.x + v1.x; a.y += v0.y + v1.y;
            a.z += v0.z + v1.z; a.w += v0.w + v1.w;
        }
    }
    if (i < end) {
        int s0 = g_src[i];
        if (act) {
            float4 v0 = ((const float4*)(feat + (size_t)s0 * D))[lane];
            a.x += v0.x; a.y += v0.y; a.z += v0.z; a.w += v0.w;
        }
    }
    if (act) {
        float inv = 1.0f / (float)max(end - beg, 1);
        float4 r;
        r.x = (a.x + b.x) * inv;
        r.y = (a.y + b.y) * inv;
        r.z = (a.z + b.z) * inv;
        r.w = (a.w + b.w) * inv;
        ((float4*)(g_agg + (size_t)warp * D))[lane] = r;
    }
}

// ---------------------------------------------------------------------------
// Register-tiled fused SAGE linear layer.
//   C[64 nodes x 96 outs] = [agg|feat][64 x 192] @ [Wl;Wr]^T + bias (+ELU)
// 128 threads = 16(node-groups) x 8(out-groups); thread tile = 4 nodes x 12
// outputs (24 u64 accs). Activations staged per 16-k chunk into transposed
// smem (software-pipelined); per k: 4 LDS.128 feed 24 FFMA2 (6x less smem
// crossbar traffic than the broadcast formulation — the measured bottleneck).
// ---------------------------------------------------------------------------
__global__ __launch_bounds__(128) void gemm_kernel(
    const float* __restrict__ x, int in_h,
    const float* __restrict__ Wl,
    const float* __restrict__ Wr,
    const float* __restrict__ bias,
    float* __restrict__ out, int out_h,
    int apply_elu)
{
    __shared__ __align__(16) float ws[D * WS];       // ws[k*WS + o] = W[o][k]
    __shared__ __align__(16) float as[16][TILE_N];   // a_s[k][node] (4 KB)
    __shared__ float bsm[D];

    const float* feat = in_h ? (const float*)g_h : x;
    const float* agg  = g_agg;
    float* dst = out_h ? (float*)g_h : out;

    int tid = threadIdx.x;

    // Stage Wl (transposed) + bias
    for (int i = tid; i < D * D; i += 128) {
        int o = i / D, k = i % D;
        ws[k * WS + o] = Wl[i];
    }
    if (tid < D) bsm[tid] = bias[tid];
    __syncthreads();

    int ng = tid & 15;            // node group 0..15 (4 nodes each)
    int og = tid >> 4;            // out group 0..7 (12 outputs each)
    int nbase = blockIdx.x * TILE_N;
    int obase = og * 12;

    // staging mapping: thread stages 8 floats of one node's k-chunk
    int slocal = tid >> 1;                       // local node 0..63
    int kpart  = (tid & 1) * 8;                  // k offset within chunk
    size_t srow = (size_t)min(nbase + slocal, N_NODES - 1) * D;

    u64 acc[4][6];
#pragma unroll
    for (int i = 0; i < 4; i++)
#pragma unroll
        for (int j = 0; j < 6; j++)
            acc[i][j] = pack2(bsm[obase + 2 * j], bsm[obase + 2 * j + 1]);

    // Prologue: load chunk 0 (agg, k 0..15)
    float4 r0 = *(const float4*)(agg + srow + kpart);
    float4 r1 = *(const float4*)(agg + srow + kpart + 4);

#pragma unroll 1
    for (int c = 0; c < 12; c++) {
        __syncthreads();                         // prev chunk consumed
        // store staged regs into transposed smem
        as[kpart + 0][slocal] = r0.x;
        as[kpart + 1][slocal] = r0.y;
        as[kpart + 2][slocal] = r0.z;
        as[kpart + 3][slocal] = r0.w;
        as[kpart + 4][slocal] = r1.x;
        as[kpart + 5][slocal] = r1.y;
        as[kpart + 6][slocal] = r1.z;
        as[kpart + 7][slocal] = r1.w;
        // prefetch next chunk
        if (c < 11) {
            int cn = c + 1;
            const float* src = (cn < 6) ? agg : feat;
            int ks = (cn - (cn < 6 ? 0 : 6)) * 16;
            r0 = *(const float4*)(src + srow + ks + kpart);
            r1 = *(const float4*)(src + srow + ks + kpart + 4);
        }
        // restage weights at the phase boundary (all threads past Wl use)
        if (c == 6) {
            for (int i = tid; i < D * D; i += 128) {
                int o = i / D, k = i % D;
                ws[k * WS + o] = Wr[i];
            }
        }
        __syncthreads();                         // a_s (and ws) ready

        int kw = (c - (c < 6 ? 0 : 6)) * 16;     // weight row base for chunk
#pragma unroll
        for (int kk = 0; kk < 16; kk++) {
            float4 a4 = *(const float4*)&as[kk][ng * 4];
            const ulonglong2* wq = (const ulonglong2*)(ws + (kw + kk) * WS + obase);
            ulonglong2 wA = wq[0];
            ulonglong2 wB = wq[1];
            ulonglong2 wC = wq[2];
            u64 a0 = pack2(a4.x, a4.x);
            u64 a1 = pack2(a4.y, a4.y);
            u64 a2 = pack2(a4.z, a4.z);
            u64 a3 = pack2(a4.w, a4.w);
            fma2(acc[0][0], a0, wA.x); fma2(acc[0][1], a0, wA.y);
            fma2(acc[0][2], a0, wB.x); fma2(acc[0][3], a0, wB.y);
            fma2(acc[0][4], a0, wC.x); fma2(acc[0][5], a0, wC.y);
            fma2(acc[1][0], a1, wA.x); fma2(acc[1][1], a1, wA.y);
            fma2(acc[1][2], a1, wB.x); fma2(acc[1][3], a1, wB.y);
            fma2(acc[1][4], a1, wC.x); fma2(acc[1][5], a1, wC.y);
            fma2(acc[2][0], a2, wA.x); fma2(acc[2][1], a2, wA.y);
            fma2(acc[2][2], a2, wB.x); fma2(acc[2][3], a2, wB.y);
            fma2(acc[2][4], a2, wC.x); fma2(acc[2][5], a2, wC.y);
            fma2(acc[3][0], a3, wA.x); fma2(acc[3][1], a3, wA.y);
            fma2(acc[3][2], a3, wB.x); fma2(acc[3][3], a3, wB.y);
            fma2(acc[3][4], a3, wC.x); fma2(acc[3][5], a3, wC.y);
        }
    }

    // Epilogue: thread writes 4 nodes x 12 outputs (3 float4 each)
#pragma unroll
    for (int i = 0; i < 4; i++) {
        int node = nbase + ng * 4 + i;
        if (node >= N_NODES) break;
        float4* o4 = (float4*)(dst + (size_t)node * D + obase);
#pragma unroll
        for (int j = 0; j < 3; j++) {
            float v0, v1, v2, v3;
            unpack2(acc[i][2 * j],     v0, v1);
            unpack2(acc[i][2 * j + 1], v2, v3);
            if (apply_elu) {
                v0 = v0 > 0.0f ? v0 : expm1f(v0);
                v1 = v1 > 0.0f ? v1 : expm1f(v1);
                v2 = v2 > 0.0f ? v2 : expm1f(v2);
                v3 = v3 > 0.0f ? v3 : expm1f(v3);
            }
            o4[j] = make_float4(v0, v1, v2, v3);
        }
    }
}

// ---------------------------------------------------------------------------
// Launch sequence (graph-capturable; kernel launches only). 6 launches;
// gemm1 sits at profile slot #4.
// ---------------------------------------------------------------------------
extern "C" void kernel_launch(void* const* d_in, const int* in_sizes, int n_in,
                              void* d_out, int out_size) {
    const float* x   = (const float*)d_in[0];
    const void*  ei  = d_in[1];
    const float* W1l = (const float*)d_in[2];
    const float* b1  = (const float*)d_in[3];
    const float* W1r = (const float*)d_in[4];
    const float* W2l = (const float*)d_in[5];
    const float* b2  = (const float*)d_in[6];
    const float* W2r = (const float*)d_in[7];
    float*       out = (float*)d_out;

    const int pb = (N_EDGES / 4 + 255) / 256;
    const int wb = (N_NODES * 32 + 255) / 256;
    const int gb = (N_NODES + TILE_N - 1) / TILE_N;

    // CSR build
    histscan_kernel<<<SCAN_B, SCAN_T>>>(ei);            // 1
    place_kernel<<<pb, 256>>>(ei);                      // 2

    // Layer 1
    gather_kernel<<<wb, 256>>>(x, 0);                   // 3
    gemm_kernel<<<gb, 128>>>(x, 0, W1l, W1r, b1, nullptr, 1, 1);   // 4 <- profiled

    // Layer 2
    gather_kernel<<<wb, 256>>>(nullptr, 1);             // 5
    gemm_kernel<<<gb, 128>>>(nullptr, 1, W2l, W2r, b2, out, 0, 0); // 6
}

// round 17
// speedup vs baseline: 1.3752x; 1.0115x over previous
#include <cuda_runtime.h>

#define N_NODES 50000
#define N_EDGES 800000
#define D 96
#define WS 100                  // padded weight stride (floats)
#define TILE_N 128              // nodes per gemm block
#define SCAN_T 1024
#define SCAN_B ((N_NODES + SCAN_T - 1) / SCAN_T)   // 49
#define HS_THREADS (SCAN_B * SCAN_T)               // 50176

typedef unsigned long long u64;

__device__ __align__(16) float g_agg[N_NODES * D];   // gathered mean features
__device__ __align__(16) float g_h[N_NODES * D];     // layer-1 activations
__device__ int g_deg[N_NODES];     // INVARIANT: all-zero at kernel_launch entry
__device__ int g_off[N_NODES + 1];
__device__ int g_cur[N_NODES];                        // placement cursors (seeded)
__device__ int g_src[N_EDGES];                        // CSR: src ids grouped by dst
__device__ int g_part[SCAN_B];
__device__ int g_flag[SCAN_B];     // INVARIANT: all-zero at entry (place clears)
__device__ int g_cnt;              // grid-barrier arrive counter (self-resetting)
__device__ int g_done;             // grid-barrier depart counter (self-resetting)

__device__ __forceinline__ u64 pack2(float lo, float hi) {
    u64 r; asm("mov.b64 %0, {%1, %2};" : "=l"(r) : "f"(lo), "f"(hi)); return r;
}
__device__ __forceinline__ void unpack2(u64 v, float& lo, float& hi) {
    asm("mov.b64 {%0, %1}, %2;" : "=f"(lo), "=f"(hi) : "l"(v));
}
__device__ __forceinline__ void fma2(u64& d, u64 a, u64 b) {
    asm("fma.rn.f32x2 %0, %1, %2, %0;" : "+l"(d) : "l"(a), "l"(b));
}
__device__ __forceinline__ int clampi(int v) {
    return min(max(v, 0), N_NODES - 1);
}

// Per-block edge-width detect: int64 small non-negative ids => odd 32-bit
// words of the first 128 words are all zero. Result broadcast via shared.
__device__ __forceinline__ int block_detect_is64(const int* __restrict__ w) {
    __shared__ int s_is64;
    if (threadIdx.x < 64) {
        int bad = (w[2 * threadIdx.x + 1] != 0) ? 1 : 0;
        unsigned m = __ballot_sync(0xffffffffu, bad);
        __shared__ unsigned sm[2];
        sm[threadIdx.x >> 5] = m;
        __syncwarp();
        if (threadIdx.x == 0) s_is64 = (sm[0] | sm[1]) ? 0 : 1;
    }
    __syncthreads();
    return s_is64;
}

// ---------------------------------------------------------------------------
// Fused histogram + scan. 49 blocks x 1024 threads (all co-resident).
// ---------------------------------------------------------------------------
__global__ __launch_bounds__(SCAN_T) void histscan_kernel(const void* __restrict__ eiv) {
    int is64 = block_detect_is64((const int*)eiv);
    int g = blockIdx.x * SCAN_T + threadIdx.x;

#pragma unroll
    for (int r = 0; r < 4; r++) {
        int grp = g + r * HS_THREADS;
        if (grp * 4 + 3 < N_EDGES) {
            int e = grp * 4;
            int d0, d1, d2, d3;
            if (is64) {
                const longlong2* p = (const longlong2*)((const long long*)eiv + N_EDGES + e);
                longlong2 a = p[0], b = p[1];
                d0 = (int)a.x; d1 = (int)a.y; d2 = (int)b.x; d3 = (int)b.y;
            } else {
                int4 a = *(const int4*)((const int*)eiv + N_EDGES + e);
                d0 = a.x; d1 = a.y; d2 = a.z; d3 = a.w;
            }
            atomicAdd(&g_deg[clampi(d0)], 1);
            atomicAdd(&g_deg[clampi(d1)], 1);
            atomicAdd(&g_deg[clampi(d2)], 1);
            atomicAdd(&g_deg[clampi(d3)], 1);
        }
    }

    __syncthreads();
    if (threadIdx.x == 0) {
        __threadfence();
        atomicAdd(&g_cnt, 1);
        while (((volatile int*)&g_cnt)[0] < SCAN_B) {}
        __threadfence();
    }
    __syncthreads();

    __shared__ int wsum[32];
    __shared__ int red[2];
    __shared__ int sbase;

    int tid = threadIdx.x;
    int bx  = blockIdx.x;
    int i = bx * SCAN_T + tid;
    int v = (i < N_NODES) ? g_deg[i] : 0;
    if (i < N_NODES) g_deg[i] = 0;           // restore invariant

    int s = v;
#pragma unroll
    for (int o = 1; o < 32; o <<= 1) {
        int u = __shfl_up_sync(0xffffffffu, s, o);
        if ((tid & 31) >= o) s += u;
    }
    if ((tid & 31) == 31) wsum[tid >> 5] = s;
    __syncthreads();
    if (tid < 32) {
        int t = wsum[tid];
#pragma unroll
        for (int o = 1; o < 32; o <<= 1) {
            int u = __shfl_up_sync(0xffffffffu, t, o);
            if (tid >= o) t += u;
        }
        wsum[tid] = t;
    }
    __syncthreads();

    if (tid == 0) {
        g_part[bx] = wsum[31];
        __threadfence();
        ((volatile int*)g_flag)[bx] = 1;
    }

    if (tid < 64) {
        int val = 0;
        if (tid < bx) {
            while (((volatile int*)g_flag)[tid] == 0) {}
            __threadfence();
            val = ((volatile int*)g_part)[tid];
        }
#pragma unroll
        for (int o = 16; o > 0; o >>= 1)
            val += __shfl_xor_sync(0xffffffffu, val, o);
        if ((tid & 31) == 0) red[tid >> 5] = val;
    }
    __syncthreads();
    if (tid == 0) sbase = red[0] + red[1];
    __syncthreads();

    int warp = tid >> 5;
    int wbase = warp ? wsum[warp - 1] : 0;
    int excl = sbase + wbase + (s - v);
    if (i < N_NODES) {
        g_off[i] = excl;
        g_cur[i] = excl;
        if (i == N_NODES - 1) g_off[N_NODES] = excl + v;
    }

    __syncthreads();
    if (tid == 0) {
        __threadfence();
        int old2 = atomicAdd(&g_done, 1);
        if (old2 == SCAN_B - 1) { g_cnt = 0; g_done = 0; }
    }
}

// ---------------------------------------------------------------------------
// place: 4 edges per thread; atomics on seeded cursors. Clears g_flag.
// ---------------------------------------------------------------------------
__global__ void place_kernel(const void* __restrict__ eiv) {
    int is64 = block_detect_is64((const int*)eiv);
    int gid = blockIdx.x * blockDim.x + threadIdx.x;
    if (gid < SCAN_B) g_flag[gid] = 0;       // restore invariant
    int e = 4 * gid;
    if (e + 3 < N_EDGES) {
        int s0, s1, s2, s3, d0, d1, d2, d3;
        if (is64) {
            const longlong2* sp = (const longlong2*)((const long long*)eiv + e);
            const longlong2* dp = (const longlong2*)((const long long*)eiv + N_EDGES + e);
            longlong2 sa = sp[0], sb = sp[1], da = dp[0], db = dp[1];
            s0 = (int)sa.x; s1 = (int)sa.y; s2 = (int)sb.x; s3 = (int)sb.y;
            d0 = (int)da.x; d1 = (int)da.y; d2 = (int)db.x; d3 = (int)db.y;
        } else {
            int4 sa = *(const int4*)((const int*)eiv + e);
            int4 da = *(const int4*)((const int*)eiv + N_EDGES + e);
            s0 = sa.x; s1 = sa.y; s2 = sa.z; s3 = sa.w;
            d0 = da.x; d1 = da.y; d2 = da.z; d3 = da.w;
        }
        s0 = clampi(s0); s1 = clampi(s1); s2 = clampi(s2); s3 = clampi(s3);
        int p0 = atomicAdd(&g_cur[clampi(d0)], 1);
        int p1 = atomicAdd(&g_cur[clampi(d1)], 1);
        int p2 = atomicAdd(&g_cur[clampi(d2)], 1);
        int p3 = atomicAdd(&g_cur[clampi(d3)], 1);
        if (p0 >= 0 && p0 < N_EDGES) g_src[p0] = s0;
        if (p1 >= 0 && p1 < N_EDGES) g_src[p1] = s1;
        if (p2 >= 0 && p2 < N_EDGES) g_src[p2] = s2;
        if (p3 >= 0 && p3 < N_EDGES) g_src[p3] = s3;
    } else {
        for (int k = e; k < N_EDGES; k++) {
            int src, dst;
            if (is64) {
                src = (int)((const long long*)eiv)[k];
                dst = (int)((const long long*)eiv)[N_EDGES + k];
            } else {
                src = ((const int*)eiv)[k];
                dst = ((const int*)eiv)[N_EDGES + k];
            }
            int pos = atomicAdd(&g_cur[clampi(dst)], 1);
            if (pos >= 0 && pos < N_EDGES) g_src[pos] = clampi(src);
        }
    }
}

// ---------------------------------------------------------------------------
// Gather mean: one warp per node; 24 active lanes, one float4 per lane per
// edge. 8-edge unroll to hide L2 latency.
// ---------------------------------------------------------------------------
__global__ __launch_bounds__(256) void gather_kernel(const float* __restrict__ x,
                                                     int from_h) {
    int warp = (blockIdx.x * blockDim.x + threadIdx.x) >> 5;
    int lane = threadIdx.x & 31;
    if (warp >= N_NODES) return;
    const float* feat = from_h ? (const float*)g_h : x;
    int beg = g_off[warp];
    int end = g_off[warp + 1];
    bool act = lane < 24;
    float4 a = make_float4(0.f, 0.f, 0.f, 0.f);
    float4 b = make_float4(0.f, 0.f, 0.f, 0.f);
    int i = beg;
    for (; i + 7 < end; i += 8) {
        int s0 = g_src[i],     s1 = g_src[i + 1], s2 = g_src[i + 2], s3 = g_src[i + 3];
        int s4 = g_src[i + 4], s5 = g_src[i + 5], s6 = g_src[i + 6], s7 = g_src[i + 7];
        if (act) {
            float4 v0 = ((const float4*)(feat + (size_t)s0 * D))[lane];
            float4 v1 = ((const float4*)(feat + (size_t)s1 * D))[lane];
            float4 v2 = ((const float4*)(feat + (size_t)s2 * D))[lane];
            float4 v3 = ((const float4*)(feat + (size_t)s3 * D))[lane];
            float4 v4 = ((const float4*)(feat + (size_t)s4 * D))[lane];
            float4 v5 = ((const float4*)(feat + (size_t)s5 * D))[lane];
            float4 v6 = ((const float4*)(feat + (size_t)s6 * D))[lane];
            float4 v7 = ((const float4*)(feat + (size_t)s7 * D))[lane];
            a.x += (v0.x + v1.x) + (v2.x + v3.x);
            a.y += (v0.y + v1.y) + (v2.y + v3.y);
            a.z += (v0.z + v1.z) + (v2.z + v3.z);
            a.w += (v0.w + v1.w) + (v2.w + v3.w);
            b.x += (v4.x + v5.x) + (v6.x + v7.x);
            b.y += (v4.y + v5.y) + (v6.y + v7.y);
            b.z += (v4.z + v5.z) + (v6.z + v7.z);
            b.w += (v4.w + v5.w) + (v6.w + v7.w);
        }
    }
    for (; i + 1 < end; i += 2) {
        int s0 = g_src[i], s1 = g_src[i + 1];
        if (act) {
            float4 v0 = ((const float4*)(feat + (size_t)s0 * D))[lane];
            float4 v1 = ((const float4*)(feat + (size_t)s1 * D))[lane];
            a.x += v0.x + v1.x; a.y += v0.y + v1.y;
            a.z += v0.z + v1.z; a.w += v0.w + v1.w;
        }
    }
    if (i < end) {
        int s0 = g_src[i];
        if (act) {
            float4 v0 = ((const float4*)(feat + (size_t)s0 * D))[lane];
            a.x += v0.x; a.y += v0.y; a.z += v0.z; a.w += v0.w;
        }
    }
    if (act) {
        float inv = 1.0f / (float)max(end - beg, 1);
        float4 r;
        r.x = (a.x + b.x) * inv;
        r.y = (a.y + b.y) * inv;
        r.z = (a.z + b.z) * inv;
        r.w = (a.w + b.w) * inv;
        ((float4*)(g_agg + (size_t)warp * D))[lane] = r;
    }
}

// ---------------------------------------------------------------------------
// Register-tiled fused SAGE linear layer, 8-node x 12-output thread tiles.
//   C[128 nodes x 96 outs] = [agg|feat][128 x 192] @ [Wl;Wr]^T + bias (+ELU)
// 128 threads = 16(node-groups) x 8(out-groups); 48 u64 accumulators.
// Per k: 2 act LDS.128 (32B) + 3 weight LDS.128 (48B) feed 48 FFMA2
// (1.67 B/FMA2 vs 2.67 in R16 — smem crossbar was the measured bottleneck).
// ---------------------------------------------------------------------------
__global__ __launch_bounds__(128) void gemm_kernel(
    const float* __restrict__ x, int in_h,
    const float* __restrict__ Wl,
    const float* __restrict__ Wr,
    const float* __restrict__ bias,
    float* __restrict__ out, int out_h,
    int apply_elu)
{
    __shared__ __align__(16) float ws[D * WS];       // ws[k*WS + o] = W[o][k]
    __shared__ __align__(16) float as[16][TILE_N];   // a_s[k][node] (8 KB)
    __shared__ float bsm[D];

    const float* feat = in_h ? (const float*)g_h : x;
    const float* agg  = g_agg;
    float* dst = out_h ? (float*)g_h : out;

    int tid = threadIdx.x;

    // Stage Wl (transposed) + bias
    for (int i = tid; i < D * D; i += 128) {
        int o = i / D, k = i % D;
        ws[k * WS + o] = Wl[i];
    }
    if (tid < D) bsm[tid] = bias[tid];
    __syncthreads();

    int ng = tid & 15;            // node group 0..15 (8 nodes each)
    int og = tid >> 4;            // out group 0..7 (12 outputs each)
    int nbase = blockIdx.x * TILE_N;
    int obase = og * 12;

    // staging: thread stages one node's full 16-k chunk (4 float4)
    size_t srow = (size_t)min(nbase + tid, N_NODES - 1) * D;

    u64 acc[8][6];
#pragma unroll
    for (int i = 0; i < 8; i++)
#pragma unroll
        for (int j = 0; j < 6; j++)
            acc[i][j] = pack2(bsm[obase + 2 * j], bsm[obase + 2 * j + 1]);

    // Prologue: load chunk 0 (agg, k 0..15)
    float4 r0 = *(const float4*)(agg + srow);
    float4 r1 = *(const float4*)(agg + srow + 4);
    float4 r2 = *(const float4*)(agg + srow + 8);
    float4 r3 = *(const float4*)(agg + srow + 12);

#pragma unroll 1
    for (int c = 0; c < 12; c++) {
        __syncthreads();                         // prev chunk consumed
        as[0][tid]  = r0.x;  as[1][tid]  = r0.y;  as[2][tid]  = r0.z;  as[3][tid]  = r0.w;
        as[4][tid]  = r1.x;  as[5][tid]  = r1.y;  as[6][tid]  = r1.z;  as[7][tid]  = r1.w;
        as[8][tid]  = r2.x;  as[9][tid]  = r2.y;  as[10][tid] = r2.z;  as[11][tid] = r2.w;
        as[12][tid] = r3.x;  as[13][tid] = r3.y;  as[14][tid] = r3.z;  as[15][tid] = r3.w;
        // prefetch next chunk
        if (c < 11) {
            int cn = c + 1;
            const float* src = (cn < 6) ? agg : feat;
            int ks = (cn - (cn < 6 ? 0 : 6)) * 16;
            r0 = *(const float4*)(src + srow + ks);
            r1 = *(const float4*)(src + srow + ks + 4);
            r2 = *(const float4*)(src + srow + ks + 8);
            r3 = *(const float4*)(src + srow + ks + 12);
        }
        // restage weights at the phase boundary
        if (c == 6) {
            for (int i = tid; i < D * D; i += 128) {
                int o = i / D, k = i % D;
                ws[k * WS + o] = Wr[i];
            }
        }
        __syncthreads();                         // a_s (and ws) ready

        int kw = (c - (c < 6 ? 0 : 6)) * 16;
#pragma unroll
        for (int kk = 0; kk < 16; kk++) {
            float4 aa = *(const float4*)&as[kk][ng * 8];
            float4 ab = *(const float4*)&as[kk][ng * 8 + 4];
            const ulonglong2* wq = (const ulonglong2*)(ws + (kw + kk) * WS + obase);
            ulonglong2 wA = wq[0];
            ulonglong2 wB = wq[1];
            ulonglong2 wC = wq[2];
            u64 p0 = pack2(aa.x, aa.x);
            u64 p1 = pack2(aa.y, aa.y);
            u64 p2 = pack2(aa.z, aa.z);
            u64 p3 = pack2(aa.w, aa.w);
            u64 p4 = pack2(ab.x, ab.x);
            u64 p5 = pack2(ab.y, ab.y);
            u64 p6 = pack2(ab.z, ab.z);
            u64 p7 = pack2(ab.w, ab.w);
            fma2(acc[0][0], p0, wA.x); fma2(acc[0][1], p0, wA.y);
            fma2(acc[0][2], p0, wB.x); fma2(acc[0][3], p0, wB.y);
            fma2(acc[0][4], p0, wC.x); fma2(acc[0][5], p0, wC.y);
            fma2(acc[1][0], p1, wA.x); fma2(acc[1][1], p1, wA.y);
            fma2(acc[1][2], p1, wB.x); fma2(acc[1][3], p1, wB.y);
            fma2(acc[1][4], p1, wC.x); fma2(acc[1][5], p1, wC.y);
            fma2(acc[2][0], p2, wA.x); fma2(acc[2][1], p2, wA.y);
            fma2(acc[2][2], p2, wB.x); fma2(acc[2][3], p2, wB.y);
            fma2(acc[2][4], p2, wC.x); fma2(acc[2][5], p2, wC.y);
            fma2(acc[3][0], p3, wA.x); fma2(acc[3][1], p3, wA.y);
            fma2(acc[3][2], p3, wB.x); fma2(acc[3][3], p3, wB.y);
            fma2(acc[3][4], p3, wC.x); fma2(acc[3][5], p3, wC.y);
            fma2(acc[4][0], p4, wA.x); fma2(acc[4][1], p4, wA.y);
            fma2(acc[4][2], p4, wB.x); fma2(acc[4][3], p4, wB.y);
            fma2(acc[4][4], p4, wC.x); fma2(acc[4][5], p4, wC.y);
            fma2(acc[5][0], p5, wA.x); fma2(acc[5][1], p5, wA.y);
            fma2(acc[5][2], p5, wB.x); fma2(acc[5][3], p5, wB.y);
            fma2(acc[5][4], p5, wC.x); fma2(acc[5][5], p5, wC.y);
            fma2(acc[6][0], p6, wA.x); fma2(acc[6][1], p6, wA.y);
            fma2(acc[6][2], p6, wB.x); fma2(acc[6][3], p6, wB.y);
            fma2(acc[6][4], p6, wC.x); fma2(acc[6][5], p6, wC.y);
            fma2(acc[7][0], p7, wA.x); fma2(acc[7][1], p7, wA.y);
            fma2(acc[7][2], p7, wB.x); fma2(acc[7][3], p7, wB.y);
            fma2(acc[7][4], p7, wC.x); fma2(acc[7][5], p7, wC.y);
        }
    }

    // Epilogue: thread writes 8 nodes x 12 outputs (3 float4 each)
#pragma unroll
    for (int i = 0; i < 8; i++) {
        int node = nbase + ng * 8 + i;
        if (node >= N_NODES) break;
        float4* o4 = (float4*)(dst + (size_t)node * D + obase);
#pragma unroll
        for (int j = 0; j < 3; j++) {
            float v0, v1, v2, v3;
            unpack2(acc[i][2 * j],     v0, v1);
            unpack2(acc[i][2 * j + 1], v2, v3);
            if (apply_elu) {
                v0 = v0 > 0.0f ? v0 : expm1f(v0);
                v1 = v1 > 0.0f ? v1 : expm1f(v1);
                v2 = v2 > 0.0f ? v2 : expm1f(v2);
                v3 = v3 > 0.0f ? v3 : expm1f(v3);
            }
            o4[j] = make_float4(v0, v1, v2, v3);
        }
    }
}

// ---------------------------------------------------------------------------
// Launch sequence (graph-capturable; kernel launches only). 6 launches;
// gemm1 sits at profile slot #4.
// ---------------------------------------------------------------------------
extern "C" void kernel_launch(void* const* d_in, const int* in_sizes, int n_in,
                              void* d_out, int out_size) {
    const float* x   = (const float*)d_in[0];
    const void*  ei  = d_in[1];
    const float* W1l = (const float*)d_in[2];
    const float* b1  = (const float*)d_in[3];
    const float* W1r = (const float*)d_in[4];
    const float* W2l = (const float*)d_in[5];
    const float* b2  = (const float*)d_in[6];
    const float* W2r = (const float*)d_in[7];
    float*       out = (float*)d_out;

    const int pb = (N_EDGES / 4 + 255) / 256;
    const int wb = (N_NODES * 32 + 255) / 256;
    const int gb = (N_NODES + TILE_N - 1) / TILE_N;

    // CSR build
    histscan_kernel<<<SCAN_B, SCAN_T>>>(ei);            // 1
    place_kernel<<<pb, 256>>>(ei);                      // 2

    // Layer 1
    gather_kernel<<<wb, 256>>>(x, 0);                   // 3
    gemm_kernel<<<gb, 128>>>(x, 0, W1l, W1r, b1, nullptr, 1, 1);   // 4 <- profiled

    // Layer 2
    gather_kernel<<<wb, 256>>>(nullptr, 1);             // 5
    gemm_kernel<<<gb, 128>>>(nullptr, 1, W2l, W2r, b2, out, 0, 0); // 6
}